// round 15
// baseline (speedup 1.0000x reference)
#include <cuda_runtime.h>
#include <cuda_fp16.h>
#include <cstdint>

#define NN 4
#define C  64
#define H  160
#define W  320
#define DISP 48
#define G  8
#define HW (H*W)
#define SMEM_BYTES (W * 16)            // 8 halfs per w position = 16B

// Swizzle for 16B rows: XOR chunk bits [4:7) with bits [7:10).
// Compute lanes step w by 4: chunks {0,4,1,5,2,6,3,7} per 8-lane phase.
// Staging lanes step w by 1: chunks (w&7)^K all distinct. Conflict-free.
__device__ __forceinline__ unsigned sw16(int w) {
    unsigned off = (unsigned)w * 16u;
    off ^= (((unsigned)w >> 3) & 7u) << 4;
    return off;
}

// fp16 dot of 8 channels (4 half2 lanes), fp32 finish.
__device__ __forceinline__ float doth(const __half2* l2, const __half2* r2) {
    __half2 a = __hmul2(l2[0], r2[0]);
    a = __hfma2(l2[1], r2[1], a);
    a = __hfma2(l2[2], r2[2], a);
    a = __hfma2(l2[3], r2[3], a);
    float2 f = __half22float2(a);
    return f.x + f.y;
}

__global__ __launch_bounds__(80, 14)
void gwc_kernel(const float* __restrict__ lg,
                const float* __restrict__ rg,
                float* __restrict__ out) {
    __shared__ __align__(16) char rS[SMEM_BYTES];

    const int h   = blockIdx.x;
    const int n   = blockIdx.y;
    const int g   = blockIdx.z;
    const int tid = threadIdx.x;
    const int w0  = tid * 4;             // this thread's 4 output columns

    // ---- l: 8 channels x 4 w via 8 LDG.128; scale 1/8; pack half2 ----
    // lw2[j][k] = (l[ch 2k], l[ch 2k+1]) at w0+j, pre-scaled.
    const float* lp = lg + ((n * C + g * 8) * H + h) * W + w0;
    __half2 lw2[4][4];
    #pragma unroll
    for (int k = 0; k < 4; ++k) {
        float4 va = *(const float4*)(lp + (2 * k) * HW);
        float4 vb = *(const float4*)(lp + (2 * k + 1) * HW);
        lw2[0][k] = __floats2half2_rn(va.x * 0.125f, vb.x * 0.125f);
        lw2[1][k] = __floats2half2_rn(va.y * 0.125f, vb.y * 0.125f);
        lw2[2][k] = __floats2half2_rn(va.z * 0.125f, vb.z * 0.125f);
        lw2[3][k] = __floats2half2_rn(va.w * 0.125f, vb.w * 0.125f);
    }

    // ---- Stage r channels as fp16, [w][8ch], swizzled (4 pos/thread) ----
    {
        const float* rbase = rg + ((n * C + g * 8) * H + h) * W;
        #pragma unroll
        for (int k = 0; k < 4; ++k) {
            int w = tid + k * 80;
            float f[8];
            #pragma unroll
            for (int c = 0; c < 8; ++c) f[c] = rbase[c * HW + w];
            uint4 hv;
            *(__half2*)&hv.x = __floats2half2_rn(f[0], f[1]);
            *(__half2*)&hv.y = __floats2half2_rn(f[2], f[3]);
            *(__half2*)&hv.z = __floats2half2_rn(f[4], f[5]);
            *(__half2*)&hv.w = __floats2half2_rn(f[6], f[7]);
            *(uint4*)(rS + sw16(w)) = hv;
        }
    }
    __syncthreads();

    // ---- Compute: 4-slot ring over disparity (slot = position & 3) ----
    __half2 r2[4][4];
    #define LDPOS(wpos, s) do {                                     \
        uint4 _hv = *(const uint4*)(rS + sw16(wpos));               \
        r2[s][0] = *(__half2*)&_hv.x; r2[s][1] = *(__half2*)&_hv.y; \
        r2[s][2] = *(__half2*)&_hv.z; r2[s][3] = *(__half2*)&_hv.w; \
    } while (0)

    #pragma unroll
    for (int j = 0; j < 4; ++j) LDPOS(w0 + j, j);

    float* op = out + (((n * G + g) * DISP) * H + h) * W + w0;

    if (w0 >= DISP) {
        // Fast path (tid >= 12): unconditional refill, no predicates.
        #pragma unroll 4
        for (int d = 0; d < DISP; ++d) {
            const int e  = d & 3;
            const int sn = (4 - e) & 3;          // slot of new position w0-d
            if (d > 0) LDPOS(w0 - d, sn);
            float4 o;
            o.x = doth(lw2[0], r2[(0 - e) & 3]);
            o.y = doth(lw2[1], r2[(1 - e) & 3]);
            o.z = doth(lw2[2], r2[(2 - e) & 3]);
            o.w = doth(lw2[3], r2[(3 - e) & 3]);
            __stcs((float4*)op, o);
            op += HW;
        }
    } else {
        #pragma unroll 4
        for (int d = 0; d < DISP; ++d) {
            const int e  = d & 3;
            const int sn = (4 - e) & 3;
            const int wn = w0 - d;
            if (d > 0 && wn >= 0) LDPOS(wn, sn);
            float4 o;
            o.x = (w0 + 0 >= d) ? doth(lw2[0], r2[(0 - e) & 3]) : 1.0f;
            o.y = (w0 + 1 >= d) ? doth(lw2[1], r2[(1 - e) & 3]) : 1.0f;
            o.z = (w0 + 2 >= d) ? doth(lw2[2], r2[(2 - e) & 3]) : 1.0f;
            o.w = (w0 + 3 >= d) ? doth(lw2[3], r2[(3 - e) & 3]) : 1.0f;
            __stcs((float4*)op, o);
            op += HW;
        }
    }
    #undef LDPOS
}

extern "C" void kernel_launch(void* const* d_in, const int* in_sizes, int n_in,
                              void* d_out, int out_size) {
    const float* l = (const float*)d_in[0];
    const float* r = (const float*)d_in[1];
    float* out = (float*)d_out;

    dim3 grid(H, NN, G);                 // 5120 CTAs: (h, n, group)
    gwc_kernel<<<grid, 80>>>(l, r, out);
}

// round 16
// speedup vs baseline: 1.3891x; 1.3891x over previous
#include <cuda_runtime.h>
#include <cuda_fp16.h>
#include <cstdint>

#define NN 4
#define C  64
#define H  160
#define W  320
#define DISP 48
#define G  8
#define HW (H*W)
#define SMEM_BYTES (W * 16)            // 8 halfs per w position = 16B

// Swizzle for 16B rows: XOR chunk bits [4:7) with bits [7:10).
// Compute lanes step w by 2 and staging lanes step w by 1: both give 8
// distinct 16B chunks per 8-lane phase -> conflict-free (R12/R13-verified).
__device__ __forceinline__ unsigned sw16(int w) {
    unsigned off = (unsigned)w * 16u;
    off ^= (((unsigned)w >> 3) & 7u) << 4;
    return off;
}

// fp16 dot of 8 channels (4 half2 lanes), fp32 finish.
__device__ __forceinline__ float doth(const __half2* l2, const __half2* r2) {
    __half2 a = __hmul2(l2[0], r2[0]);
    a = __hfma2(l2[1], r2[1], a);
    a = __hfma2(l2[2], r2[2], a);
    a = __hfma2(l2[3], r2[3], a);
    float2 f = __half22float2(a);
    return f.x + f.y;
}

__global__ __launch_bounds__(160, 8)
void gwc_kernel(const float* __restrict__ lg,
                const float* __restrict__ rg,
                float* __restrict__ out) {
    __shared__ __align__(16) char rS[SMEM_BYTES];

    const int h   = blockIdx.x;
    const int n   = blockIdx.y;
    const int g   = blockIdx.z;
    const int tid = threadIdx.x;
    const int w0  = tid * 2;             // this thread's 2 output columns

    // ---- l: 8 coalesced LDG.64 (channel pairs), scale 1/8, pack half2 ----
    // lA2[j] = (l[2j], l[2j+1]) at w0 ; lB2[j] = same at w0+1.
    const float* lp = lg + ((n * C + g * 8) * H + h) * W + w0;
    __half2 lA2[4], lB2[4];
    #pragma unroll
    for (int j = 0; j < 4; ++j) {
        float2 v0 = *(const float2*)(lp + (2 * j) * HW);
        float2 v1 = *(const float2*)(lp + (2 * j + 1) * HW);
        lA2[j] = __floats2half2_rn(v0.x * 0.125f, v1.x * 0.125f);
        lB2[j] = __floats2half2_rn(v0.y * 0.125f, v1.y * 0.125f);
    }

    // ---- Stage r channels as fp16, [w][8ch], swizzled ----
    {
        const float* rbase = rg + ((n * C + g * 8) * H + h) * W;
        #pragma unroll
        for (int k = 0; k < 2; ++k) {
            int w = tid + k * 160;
            float f[8];
            #pragma unroll
            for (int c = 0; c < 8; ++c) f[c] = rbase[c * HW + w];
            uint4 hv;
            *(__half2*)&hv.x = __floats2half2_rn(f[0], f[1]);
            *(__half2*)&hv.y = __floats2half2_rn(f[2], f[3]);
            *(__half2*)&hv.z = __floats2half2_rn(f[4], f[5]);
            *(__half2*)&hv.w = __floats2half2_rn(f[6], f[7]);
            *(uint4*)(rS + sw16(w)) = hv;
        }
    }
    __syncthreads();

    // ---- Compute: 2-slot sliding window, all-fp16 ring ----
    __half2 r2[2][4];                    // slot p = parity of r position
    #define LDPOS(wpos, s) do {                                  \
        uint4 _hv = *(const uint4*)(rS + sw16(wpos));            \
        r2[s][0] = *(__half2*)&_hv.x; r2[s][1] = *(__half2*)&_hv.y; \
        r2[s][2] = *(__half2*)&_hv.z; r2[s][3] = *(__half2*)&_hv.w; \
    } while (0)

    LDPOS(w0,     0);
    LDPOS(w0 + 1, 1);

    float* op = out + (((n * G + g) * DISP) * H + h) * W + w0;

    if (w0 >= DISP) {
        #pragma unroll 4
        for (int d2 = 0; d2 < DISP; d2 += 2) {
            // d = d2 (even): output x parity 0, y parity 1
            if (d2 > 0) LDPOS(w0 - d2, 0);
            float2 o01;
            o01.x = doth(lA2, r2[0]);
            o01.y = doth(lB2, r2[1]);
            __stcs((float2*)op, o01);

            // d = d2+1: new position w0-d2-1 has parity 1
            LDPOS(w0 - d2 - 1, 1);
            o01.x = doth(lA2, r2[1]);
            o01.y = doth(lB2, r2[0]);
            __stcs((float2*)(op + HW), o01);

            op += 2 * HW;
        }
    } else {
        #pragma unroll 4
        for (int d2 = 0; d2 < DISP; d2 += 2) {
            const int wn0 = w0 - d2;
            if (d2 > 0 && wn0 >= 0) LDPOS(wn0, 0);
            float2 o01;
            o01.x = (w0     >= d2) ? doth(lA2, r2[0]) : 1.0f;
            o01.y = (w0 + 1 >= d2) ? doth(lB2, r2[1]) : 1.0f;
            __stcs((float2*)op, o01);

            const int wn1 = w0 - d2 - 1;
            if (wn1 >= 0) LDPOS(wn1, 1);
            o01.x = (w0     >= d2 + 1) ? doth(lA2, r2[1]) : 1.0f;
            o01.y = (w0 + 1 >= d2 + 1) ? doth(lB2, r2[0]) : 1.0f;
            __stcs((float2*)(op + HW), o01);

            op += 2 * HW;
        }
    }
    #undef LDPOS
}

extern "C" void kernel_launch(void* const* d_in, const int* in_sizes, int n_in,
                              void* d_out, int out_size) {
    const float* l = (const float*)d_in[0];
    const float* r = (const float*)d_in[1];
    float* out = (float*)d_out;

    dim3 grid(H, NN, G);                 // 5120 CTAs: (h, n, group)
    gwc_kernel<<<grid, 160>>>(l, r, out);
}